// round 6
// baseline (speedup 1.0000x reference)
#include <cuda_runtime.h>
#include <cuda_fp16.h>
#include <math.h>

// ---------------------------------------------------------------------------
// DTree forward. Round 6: R5 + (a) parallel k0, (b) leaf-chunked k6 (1024 CTAs
// -> 93% SM fill) with deterministic partial reduction k7, (c) k1b+k2 merged.
// All GEMMs on mma.sync.m16n8k16.f16 with pre-permuted B fragments, no smem.
// ---------------------------------------------------------------------------

#define BATCH   8192
#define DIN     512
#define D1      513
#define HP      272      // g_hh row stride in u32 (half2 pairs): 544 halves
#define NKT     17
#define NODES   127
#define LEAVES  128
#define DOUT    256
#define NCHUNK  8        // leaf chunks in k6
#define LPC     16       // leaves per chunk
#define CITERS  (NKT * LPC)   // 272

typedef unsigned long long u64;
typedef unsigned int u32;

// -------------------- scratch (device globals; no allocation) --------------
__device__ __align__(16) u32 g_hh[BATCH * HP];          // 8.9 MB packed half2 h
__device__ __align__(16) u32 g_Bp[LEAVES * NKT * 4096]; // 35.7 MB leaf B fragments
__device__ __align__(16) u32 g_Bpre[16 * 8192];         // 0.52 MB W_pre fragments
__device__ __align__(16) u32 g_Brw[NKT * 2048];         // 0.14 MB right_w fragments
__device__ __align__(16) float g_part[NCHUNK * BATCH * DOUT]; // 67 MB partials
__device__ u32 g_swh2[LEAVES * BATCH];                  // 4.2 MB (s,s) half2
__device__ float g_right[BATCH * 128];
__device__ float g_invh[BATCH];
__device__ float g_invw[NODES];
__device__ float g_entpart[1024];
__device__ float g_scale;

// -------------------- helpers ----------------------------------------------
__device__ __forceinline__ u32 h2(float lo, float hi) {
    u32 r; asm("cvt.rn.f16x2.f32 %0, %1, %2;" : "=r"(r) : "f"(hi), "f"(lo)); return r;
}
__device__ __forceinline__ u32 hmul2(u32 a, u32 b) {
    u32 r; asm("mul.f16x2 %0, %1, %2;" : "=r"(r) : "r"(a), "r"(b)); return r;
}
__device__ __forceinline__ float2 h2f(u32 v) {
    __half2 h = *reinterpret_cast<__half2*>(&v);
    return __half22float2(h);
}
__device__ __forceinline__ void mma_f16(float* c, u32 a0, u32 a1, u32 a2, u32 a3,
                                        u32 b0, u32 b1) {
    asm volatile("mma.sync.aligned.m16n8k16.row.col.f32.f16.f16.f32 "
                 "{%0,%1,%2,%3}, {%4,%5,%6,%7}, {%8,%9}, {%0,%1,%2,%3};"
                 : "+f"(c[0]), "+f"(c[1]), "+f"(c[2]), "+f"(c[3])
                 : "r"(a0), "r"(a1), "r"(a2), "r"(a3), "r"(b0), "r"(b1));
}

// Fragment addressing convention (m16n8k16):
//   B frag u32 index = (((tile*NW + nw)*2 + ks)*2 + h)*128 + lane*4 + r
//   nt = h*2 + (r>>1); reg = r&1
//   n  = nw*32 + nt*8 + (lane>>2)
//   d  = kt*32 + ks*16 + (lane&3)*2 + reg*8   (value = half2(W[n][d], W[n][d+1]))

// ============================================================================
// k_prep: leaf B fragments. tile = l*17 + kt, NW = 8.
// ============================================================================
__global__ void k_prep(const float* __restrict__ Wl, const float* __restrict__ bl) {
    u32 o = blockIdx.x * 256 + threadIdx.x;
    u32 r = o & 3, lane = (o >> 2) & 31;
    u32 h = (o >> 7) & 1, ks = (o >> 8) & 1, nw = (o >> 9) & 7;
    u32 t = o >> 12;
    u32 kt = t % 17, l = t / 17;
    u32 nt = h * 2 + (r >> 1), reg = r & 1;
    int n = (int)(nw * 32 + nt * 8 + (lane >> 2));
    int row = (int)(l * 256 + n);
    int d = (int)(kt * 32 + ks * 16 + (lane & 3) * 2 + reg * 8);
    float v0 = 0.0f, v1 = 0.0f;
    if (d < D1)           v0 = Wl[(size_t)row * D1 + d];
    else if (d == D1)     v0 = bl[row];
    if (d + 1 < D1)       v1 = Wl[(size_t)row * D1 + d + 1];
    else if (d + 1 == D1) v1 = bl[row];
    g_Bp[o] = h2(v0, v1);
}

// ============================================================================
// k_prep1: W_pre fragments (512x512). tile = kt, NW = 16.
// ============================================================================
__global__ void k_prep1(const float* __restrict__ Wp) {
    u32 o = blockIdx.x * 256 + threadIdx.x;   // < 131072
    u32 r = o & 3, lane = (o >> 2) & 31;
    u32 h = (o >> 7) & 1, ks = (o >> 8) & 1, nw = (o >> 9) & 15;
    u32 kt = o >> 13;
    u32 nt = h * 2 + (r >> 1), reg = r & 1;
    int n = (int)(nw * 32 + nt * 8 + (lane >> 2));
    int d = (int)(kt * 32 + ks * 16 + (lane & 3) * 2 + reg * 8);
    g_Bpre[o] = h2(Wp[(size_t)n * DIN + d], Wp[(size_t)n * DIN + d + 1]);
}

// ============================================================================
// k_prep3: right_w fragments (127x513 padded to 128x544). tile = kt, NW = 4.
// ============================================================================
__global__ void k_prep3(const float* __restrict__ rw) {
    u32 o = blockIdx.x * 256 + threadIdx.x;   // < 34816
    u32 r = o & 3, lane = (o >> 2) & 31;
    u32 h = (o >> 7) & 1, ks = (o >> 8) & 1, nw = (o >> 9) & 3;
    u32 kt = o >> 11;
    u32 nt = h * 2 + (r >> 1), reg = r & 1;
    int n = (int)(nw * 32 + nt * 8 + (lane >> 2));
    int d = (int)(kt * 32 + ks * 16 + (lane & 3) * 2 + reg * 8);
    float v0 = (n < NODES && d < D1)     ? rw[(size_t)n * D1 + d]     : 0.0f;
    float v1 = (n < NODES && d + 1 < D1) ? rw[(size_t)n * D1 + d + 1] : 0.0f;
    g_Brw[o] = h2(v0, v1);
}

// ============================================================================
// k0: right_w inverse row norms -- one block (128 thr) per node
// ============================================================================
__global__ void k0_init(const float* __restrict__ right_w) {
    __shared__ float sm[4];
    int n = blockIdx.x, tid = threadIdx.x;
    const float* wr = right_w + (size_t)n * D1;
    float s = 0.0f;
    for (int d = tid; d < D1; d += 128) { float v = wr[d]; s += v * v; }
    #pragma unroll
    for (int o = 16; o > 0; o >>= 1) s += __shfl_xor_sync(0xffffffffu, s, o);
    if ((tid & 31) == 0) sm[tid >> 5] = s;
    __syncthreads();
    if (tid == 0)
        g_invw[n] = 1.0f / fmaxf(sqrtf(sm[0] + sm[1] + sm[2] + sm[3]), 1e-12f);
}

// ============================================================================
// k1: h[:,0:512] = relu(x @ W_pre[0:512]^T + b_pre) -> g_hh pairs 0..255
// ============================================================================
__global__ __launch_bounds__(256, 1) void k1_pre(const float* __restrict__ x,
                                                 const float* __restrict__ bp) {
    int tid = threadIdx.x, wid = tid >> 5, lane = tid & 31;
    int mw = wid >> 2, nwl = wid & 3;
    int m0 = blockIdx.y * 128;
    int nw = blockIdx.x * 4 + nwl;
    int rbase = m0 + mw * 64 + (lane >> 2);

    const u32* Bb = g_Bpre + (size_t)nw * 512 + lane * 4;
    const float* Xb = x + (size_t)rbase * DIN + (lane & 3) * 2;

    float acc[4][4][4];
    #pragma unroll
    for (int a = 0; a < 4; a++)
        #pragma unroll
        for (int b = 0; b < 4; b++)
            #pragma unroll
            for (int c = 0; c < 4; c++) acc[a][b][c] = 0.0f;

    uint4 bb[2][2][2];
    #pragma unroll
    for (int ks = 0; ks < 2; ks++)
        #pragma unroll
        for (int h = 0; h < 2; h++)
            bb[0][ks][h] = __ldg((const uint4*)(Bb + ks * 256 + h * 128));

    #pragma unroll 2
    for (int kt = 0; kt < 16; kt++) {
        int pb = kt & 1, nb = pb ^ 1;
        if (kt + 1 < 16) {
            const u32* t = Bb + (size_t)(kt + 1) * 8192;
            #pragma unroll
            for (int ks = 0; ks < 2; ks++)
                #pragma unroll
                for (int h = 0; h < 2; h++)
                    bb[nb][ks][h] = __ldg((const uint4*)(t + ks * 256 + h * 128));
        }
        u32 av[4][2][2][2];
        #pragma unroll
        for (int mt = 0; mt < 4; mt++)
            #pragma unroll
            for (int rhl = 0; rhl < 2; rhl++)
                #pragma unroll
                for (int ks = 0; ks < 2; ks++)
                    #pragma unroll
                    for (int reg = 0; reg < 2; reg++) {
                        float2 f = *(const float2*)(Xb + (size_t)(mt * 16 + rhl * 8) * DIN
                                                    + kt * 32 + ks * 16 + reg * 8);
                        av[mt][rhl][ks][reg] = h2(f.x, f.y);
                    }
        #pragma unroll
        for (int ks = 0; ks < 2; ks++)
            #pragma unroll
            for (int h = 0; h < 2; h++) {
                uint4 B = bb[pb][ks][h];
                #pragma unroll
                for (int mt = 0; mt < 4; mt++) {
                    mma_f16(acc[mt][h * 2],     av[mt][0][ks][0], av[mt][1][ks][0],
                            av[mt][0][ks][1], av[mt][1][ks][1], B.x, B.y);
                    mma_f16(acc[mt][h * 2 + 1], av[mt][0][ks][0], av[mt][1][ks][0],
                            av[mt][0][ks][1], av[mt][1][ks][1], B.z, B.w);
                }
            }
    }

    int ncol = blockIdx.x * 128 + nwl * 32 + (lane & 3) * 2;
    #pragma unroll
    for (int mt = 0; mt < 4; mt++)
        #pragma unroll
        for (int half = 0; half < 2; half++) {
            int row = rbase + mt * 16 + half * 8;
            #pragma unroll
            for (int nt = 0; nt < 4; nt++) {
                int n = ncol + nt * 8;
                float v0 = fmaxf(acc[mt][nt][half * 2]     + __ldg(bp + n),     0.0f);
                float v1 = fmaxf(acc[mt][nt][half * 2 + 1] + __ldg(bp + n + 1), 0.0f);
                g_hh[(size_t)row * HP + (n >> 1)] = h2(v0, v1);
            }
        }
}

// ============================================================================
// k1b2: h[:,512] dot + pad writes + row inverse-norm (merged k1b+k2).
// One warp per row.
// ============================================================================
__global__ void k1b2(const float* __restrict__ x, const float* __restrict__ Wp,
                     const float* __restrict__ bp) {
    int w = threadIdx.x >> 5, lane = threadIdx.x & 31;
    int b = blockIdx.x * 8 + w;
    const float* xr = x + (size_t)b * DIN;
    const float* wr = Wp + (size_t)512 * DIN;
    float s = 0.0f;
    #pragma unroll 4
    for (int d = lane; d < DIN; d += 32) s += xr[d] * wr[d];
    #pragma unroll
    for (int o = 16; o > 0; o >>= 1) s += __shfl_xor_sync(0xffffffffu, s, o);
    float h512 = fmaxf(s + __ldg(bp + 512), 0.0f);   // uniform across warp

    u32* row = g_hh + (size_t)b * HP;
    if (lane == 0) row[256] = h2(h512, 1.0f);
    else if (lane < 16) row[256 + lane] = 0u;

    // row norm over pairs 0..255 (written by k1) + h512
    float t = 0.0f;
    for (int i = lane; i < 256; i += 32) {
        float2 f = h2f(row[i]);
        t += f.x * f.x + f.y * f.y;
    }
    #pragma unroll
    for (int o = 16; o > 0; o >>= 1) t += __shfl_xor_sync(0xffffffffu, t, o);
    if (lane == 0) g_invh[b] = 1.0f / fmaxf(sqrtf(t + h512 * h512), 1e-12f);
}

// ============================================================================
// k3: right[b,n] = invh[b]*invw[n]*(h . right_w[n])  -- fp16 mma
// ============================================================================
__global__ __launch_bounds__(256, 1) void k3_right() {
    int tid = threadIdx.x, wid = tid >> 5, lane = tid & 31;
    int mw = wid >> 2, nwl = wid & 3;
    int m0 = blockIdx.y * 128;
    int rbase = m0 + mw * 64 + (lane >> 2);

    const u32* Bb = g_Brw + (size_t)nwl * 512 + lane * 4;
    const u32* Hb = g_hh + (size_t)rbase * HP + (lane & 3);

    float acc[4][4][4];
    #pragma unroll
    for (int a = 0; a < 4; a++)
        #pragma unroll
        for (int b = 0; b < 4; b++)
            #pragma unroll
            for (int c = 0; c < 4; c++) acc[a][b][c] = 0.0f;

    #pragma unroll 1
    for (int kt = 0; kt < 17; kt++) {
        uint4 bb[2][2];
        #pragma unroll
        for (int ks = 0; ks < 2; ks++)
            #pragma unroll
            for (int h = 0; h < 2; h++)
                bb[ks][h] = __ldg((const uint4*)(Bb + (size_t)kt * 2048 + ks * 256 + h * 128));
        u32 hv[4][2][2][2];
        #pragma unroll
        for (int mt = 0; mt < 4; mt++)
            #pragma unroll
            for (int rhl = 0; rhl < 2; rhl++)
                #pragma unroll
                for (int ks = 0; ks < 2; ks++)
                    #pragma unroll
                    for (int reg = 0; reg < 2; reg++)
                        hv[mt][rhl][ks][reg] = __ldg(Hb + (size_t)(mt * 16 + rhl * 8) * HP
                                                     + kt * 16 + ks * 8 + reg * 4);
        #pragma unroll
        for (int ks = 0; ks < 2; ks++)
            #pragma unroll
            for (int h = 0; h < 2; h++) {
                uint4 B = bb[ks][h];
                #pragma unroll
                for (int mt = 0; mt < 4; mt++) {
                    mma_f16(acc[mt][h * 2],     hv[mt][0][ks][0], hv[mt][1][ks][0],
                            hv[mt][0][ks][1], hv[mt][1][ks][1], B.x, B.y);
                    mma_f16(acc[mt][h * 2 + 1], hv[mt][0][ks][0], hv[mt][1][ks][0],
                            hv[mt][0][ks][1], hv[mt][1][ks][1], B.z, B.w);
                }
            }
    }

    #pragma unroll
    for (int mt = 0; mt < 4; mt++)
        #pragma unroll
        for (int half = 0; half < 2; half++) {
            int row = rbase + mt * 16 + half * 8;
            float ih = g_invh[row];
            #pragma unroll
            for (int nt = 0; nt < 4; nt++) {
                int n = nwl * 32 + nt * 8 + (lane & 3) * 2;
                if (n < NODES)
                    g_right[(size_t)row * 128 + n] = acc[mt][nt][half * 2] * ih * g_invw[n];
                if (n + 1 < NODES)
                    g_right[(size_t)row * 128 + n + 1] = acc[mt][nt][half * 2 + 1] * ih * g_invw[n + 1];
            }
        }
}

// ============================================================================
// k4: routing -> g_swh2 (packed (s,s) half2, [l][b]), entropy partials
// ============================================================================
__global__ __launch_bounds__(256) void k4_route(const int* __restrict__ ridx,
                                                const int* __restrict__ rside) {
    __shared__ int s_idx[LEAVES * 7];
    __shared__ int s_side[LEAVES * 7];
    __shared__ float s_lr[8][128];
    __shared__ float s_ll[8][128];
    __shared__ float s_ent[8];

    int tid = threadIdx.x;
    for (int t = tid; t < LEAVES * 7; t += 256) { s_idx[t] = ridx[t]; s_side[t] = rside[t]; }
    __syncthreads();

    int w = tid / 32, lane = tid % 32;
    int b = blockIdx.x * 8 + w;

    for (int n = lane; n < NODES; n += 32) {
        float r = g_right[b * 128 + n];
        float rd = 0.5f * (1.0f - r);
        float ld = 0.5f * (1.0f + r);
        s_lr[w][n] = logf(fminf(fmaxf(rd, 0.01f), 0.99f));
        s_ll[w][n] = logf(fminf(fmaxf(ld, 0.01f), 0.99f));
    }
    __syncwarp();

    float ent = 0.0f;
    for (int li = lane; li < LEAVES; li += 32) {
        float lp = 0.0f;
        #pragma unroll
        for (int j = 0; j < 7; j++) {
            int node = s_idx[li * 7 + j];
            int side = s_side[li * 7 + j];
            lp += side ? s_ll[w][node] : s_lr[w][node];
        }
        float s = expf(lp);
        g_swh2[li * BATCH + b] = h2(s, s);
        ent -= s * lp;
    }
    #pragma unroll
    for (int o = 16; o > 0; o >>= 1) ent += __shfl_xor_sync(0xffffffffu, ent, o);
    if (lane == 0) s_ent[w] = ent;
    __syncthreads();
    if (tid == 0) {
        float t = 0.0f;
        #pragma unroll
        for (int i = 0; i < 8; i++) t += s_ent[i];
        g_entpart[blockIdx.x] = t;
    }
}

// ============================================================================
// k5: deterministic entropy reduction -> scale scalar
// ============================================================================
__global__ void k5_scale() {
    __shared__ float sm[256];
    float s = 0.0f;
    for (int i = threadIdx.x; i < 1024; i += 256) s += g_entpart[i];
    sm[threadIdx.x] = s;
    __syncthreads();
    for (int st = 128; st > 0; st >>= 1) {
        if (threadIdx.x < st) sm[threadIdx.x] += sm[threadIdx.x + st];
        __syncthreads();
    }
    if (threadIdx.x == 0) {
        float max_ent = (128.0f / 6.0f) * logf(6.0f);
        g_scale = 1.0f + (sm[0] / (float)BATCH) / max_ent;
    }
}

// ============================================================================
// k6: fp16 mma leaf contraction, leaf-chunked (16 leaves / CTA).
// grid (16 = 2 nh x 8 chunks, 64 m-tiles), 8 warps, warp tile 64m x 32n.
// Writes fp32 partials to g_part[chunk] (deterministic, no atomics).
// ============================================================================
__global__ __launch_bounds__(256, 1) void k6_mma() {
    int tid = threadIdx.x, wid = tid >> 5, lane = tid & 31;
    int mw = wid >> 2, nwl = wid & 3;
    int c = blockIdx.x & 7;          // leaf chunk
    int nh = blockIdx.x >> 3;        // n half
    int m0 = blockIdx.y * 128;
    int l0 = c * LPC;
    int nw = nh * 4 + nwl;
    int rbase = m0 + mw * 64 + (lane >> 2);

    const u32* Bb = g_Bp + (size_t)nw * 512 + lane * 4;     // + (l*17+kt)*4096
    const u32* SWb = g_swh2 + rbase;
    const u32* Hb = g_hh + (size_t)rbase * HP + (lane & 3);

    float acc[4][4][4];
    #pragma unroll
    for (int a = 0; a < 4; a++)
        #pragma unroll
        for (int b = 0; b < 4; b++)
            #pragma unroll
            for (int q = 0; q < 4; q++) acc[a][b][q] = 0.0f;

    uint4 bb[2][2][2];       // [buf][ks][h]
    u32 sw[2][8];            // [buf][mt*2 + rhl]
    u32 hv[4][2][2][2];      // [mt][rhl][ks][reg]

    // preload it=0 (kt=0, l=l0)
    {
        const u32* t = Bb + (size_t)(l0 * 17) * 4096;
        #pragma unroll
        for (int ks = 0; ks < 2; ks++)
            #pragma unroll
            for (int h = 0; h < 2; h++)
                bb[0][ks][h] = __ldg((const uint4*)(t + ks * 256 + h * 128));
        const u32* sp = SWb + (size_t)l0 * BATCH;
        #pragma unroll
        for (int j = 0; j < 8; j++)
            sw[0][j] = __ldg(sp + (j >> 1) * 16 + (j & 1) * 8);
    }

    int it = 0;
    #pragma unroll 1
    for (int kt = 0; kt < NKT; kt++) {
        #pragma unroll
        for (int mt = 0; mt < 4; mt++)
            #pragma unroll
            for (int rhl = 0; rhl < 2; rhl++)
                #pragma unroll
                for (int ks = 0; ks < 2; ks++)
                    #pragma unroll
                    for (int reg = 0; reg < 2; reg++)
                        hv[mt][rhl][ks][reg] = __ldg(Hb + (size_t)(mt * 16 + rhl * 8) * HP
                                                     + kt * 16 + ks * 8 + reg * 4);
        #pragma unroll 2
        for (int li = 0; li < LPC; li++) {
            int pb = it & 1, nb = pb ^ 1;
            int nit = it + 1;
            if (nit < CITERS) {
                int nl = l0 + (nit & (LPC - 1));
                int nkt = nit >> 4;
                const u32* t = Bb + (size_t)(nl * 17 + nkt) * 4096;
                #pragma unroll
                for (int ks = 0; ks < 2; ks++)
                    #pragma unroll
                    for (int h = 0; h < 2; h++)
                        bb[nb][ks][h] = __ldg((const uint4*)(t + ks * 256 + h * 128));
                const u32* sp = SWb + (size_t)nl * BATCH;
                #pragma unroll
                for (int j = 0; j < 8; j++)
                    sw[nb][j] = __ldg(sp + (j >> 1) * 16 + (j & 1) * 8);
            }
            #pragma unroll
            for (int ks = 0; ks < 2; ks++) {
                u32 A0[4], A1[4], A2[4], A3[4];
                #pragma unroll
                for (int mt = 0; mt < 4; mt++) {
                    A0[mt] = hmul2(hv[mt][0][ks][0], sw[pb][mt * 2]);
                    A1[mt] = hmul2(hv[mt][1][ks][0], sw[pb][mt * 2 + 1]);
                    A2[mt] = hmul2(hv[mt][0][ks][1], sw[pb][mt * 2]);
                    A3[mt] = hmul2(hv[mt][1][ks][1], sw[pb][mt * 2 + 1]);
                }
                #pragma unroll
                for (int h = 0; h < 2; h++) {
                    uint4 B = bb[pb][ks][h];
                    #pragma unroll
                    for (int mt = 0; mt < 4; mt++) {
                        mma_f16(acc[mt][h * 2],     A0[mt], A1[mt], A2[mt], A3[mt], B.x, B.y);
                        mma_f16(acc[mt][h * 2 + 1], A0[mt], A1[mt], A2[mt], A3[mt], B.z, B.w);
                    }
                }
            }
            it++;
        }
    }

    float* part = g_part + (size_t)c * BATCH * DOUT;
    int ncol = nh * 128 + nwl * 32 + (lane & 3) * 2;
    #pragma unroll
    for (int mt = 0; mt < 4; mt++)
        #pragma unroll
        for (int half = 0; half < 2; half++) {
            int row = rbase + mt * 16 + half * 8;
            float* op = part + (size_t)row * DOUT + ncol;
            #pragma unroll
            for (int nt = 0; nt < 4; nt++) {
                float2 v;
                v.x = acc[mt][nt][half * 2];
                v.y = acc[mt][nt][half * 2 + 1];
                *(float2*)(op + nt * 8) = v;
            }
        }
}

// ============================================================================
// k7: out = scale * sum_{c=0..7} g_part[c]   (fixed order -> deterministic)
// ============================================================================
__global__ void k7_reduce(float* __restrict__ out) {
    size_t i = ((size_t)blockIdx.x * 256 + threadIdx.x) * 4;   // float4 per thread
    float4 s = make_float4(0.f, 0.f, 0.f, 0.f);
    #pragma unroll
    for (int c = 0; c < NCHUNK; c++) {
        float4 p = __ldg((const float4*)(g_part + (size_t)c * BATCH * DOUT + i));
        s.x += p.x; s.y += p.y; s.z += p.z; s.w += p.w;
    }
    float sc = g_scale;
    s.x *= sc; s.y *= sc; s.z *= sc; s.w *= sc;
    *(float4*)(out + i) = s;
}

// ============================================================================
extern "C" void kernel_launch(void* const* d_in, const int* in_sizes, int n_in,
                              void* d_out, int out_size) {
    const float* x      = (const float*)d_in[0];
    const float* W_pre  = (const float*)d_in[1];
    const float* b_pre  = (const float*)d_in[2];
    const float* rw     = (const float*)d_in[3];
    const float* W_leaf = (const float*)d_in[4];
    const float* b_leaf = (const float*)d_in[5];
    const int*   ridx   = (const int*)d_in[6];
    const int*   rside  = (const int*)d_in[7];
    float* out = (float*)d_out;

    k_prep<<<34816, 256>>>(W_leaf, b_leaf);
    k_prep1<<<512, 256>>>(W_pre);
    k_prep3<<<136, 256>>>(rw);
    k0_init<<<NODES, 128>>>(rw);
    k1_pre<<<dim3(4, 64), 256>>>(x, b_pre);
    k1b2<<<1024, 256>>>(x, W_pre, b_pre);
    k3_right<<<dim3(1, 64), 256>>>();
    k4_route<<<1024, 256>>>(ridx, rside);
    k5_scale<<<1, 256>>>();
    k6_mma<<<dim3(16, 64), 256>>>();
    k7_reduce<<<2048, 256>>>(out);
}

// round 7
// speedup vs baseline: 1.5673x; 1.5673x over previous
#include <cuda_runtime.h>
#include <cuda_fp16.h>
#include <math.h>

// ---------------------------------------------------------------------------
// DTree forward. Round 7: R5 k6 (full-leaf loop, best measured) + R6's
// verified wins (parallel k0, merged k1b2). Leaf-chunk experiment reverted:
// it multiplied h-operand re-reads 8x and regressed.
// All GEMMs on mma.sync.m16n8k16.f16 with pre-permuted B fragments, no smem.
// ---------------------------------------------------------------------------

#define BATCH   8192
#define DIN     512
#define D1      513
#define HP      272      // g_hh row stride in u32 (half2 pairs): 544 halves
#define NKT     17
#define NODES   127
#define LEAVES  128
#define DOUT    256
#define ITERS   (NKT * LEAVES)   // 2176

typedef unsigned long long u64;
typedef unsigned int u32;

// -------------------- scratch (device globals; no allocation) --------------
__device__ __align__(16) u32 g_hh[BATCH * HP];          // 8.9 MB packed half2 h
__device__ __align__(16) u32 g_Bp[LEAVES * NKT * 4096]; // 35.7 MB leaf B fragments
__device__ __align__(16) u32 g_Bpre[16 * 8192];         // 0.52 MB W_pre fragments
__device__ __align__(16) u32 g_Brw[NKT * 2048];         // 0.14 MB right_w fragments
__device__ u32 g_swh2[LEAVES * BATCH];                  // 4.2 MB (s,s) half2
__device__ float g_right[BATCH * 128];
__device__ float g_invh[BATCH];
__device__ float g_invw[NODES];
__device__ float g_entpart[1024];
__device__ float g_scale;

// -------------------- helpers ----------------------------------------------
__device__ __forceinline__ u32 h2(float lo, float hi) {
    u32 r; asm("cvt.rn.f16x2.f32 %0, %1, %2;" : "=r"(r) : "f"(hi), "f"(lo)); return r;
}
__device__ __forceinline__ u32 hmul2(u32 a, u32 b) {
    u32 r; asm("mul.f16x2 %0, %1, %2;" : "=r"(r) : "r"(a), "r"(b)); return r;
}
__device__ __forceinline__ float2 h2f(u32 v) {
    __half2 h = *reinterpret_cast<__half2*>(&v);
    return __half22float2(h);
}
__device__ __forceinline__ void mma_f16(float* c, u32 a0, u32 a1, u32 a2, u32 a3,
                                        u32 b0, u32 b1) {
    asm volatile("mma.sync.aligned.m16n8k16.row.col.f32.f16.f16.f32 "
                 "{%0,%1,%2,%3}, {%4,%5,%6,%7}, {%8,%9}, {%0,%1,%2,%3};"
                 : "+f"(c[0]), "+f"(c[1]), "+f"(c[2]), "+f"(c[3])
                 : "r"(a0), "r"(a1), "r"(a2), "r"(a3), "r"(b0), "r"(b1));
}

// Fragment addressing convention (m16n8k16):
//   B frag u32 index = (((tile*NW + nw)*2 + ks)*2 + h)*128 + lane*4 + r
//   nt = h*2 + (r>>1); reg = r&1
//   n  = nw*32 + nt*8 + (lane>>2)
//   d  = kt*32 + ks*16 + (lane&3)*2 + reg*8   (value = half2(W[n][d], W[n][d+1]))

// ============================================================================
// k_prep: leaf B fragments. tile = l*17 + kt, NW = 8.
// ============================================================================
__global__ void k_prep(const float* __restrict__ Wl, const float* __restrict__ bl) {
    u32 o = blockIdx.x * 256 + threadIdx.x;
    u32 r = o & 3, lane = (o >> 2) & 31;
    u32 h = (o >> 7) & 1, ks = (o >> 8) & 1, nw = (o >> 9) & 7;
    u32 t = o >> 12;
    u32 kt = t % 17, l = t / 17;
    u32 nt = h * 2 + (r >> 1), reg = r & 1;
    int n = (int)(nw * 32 + nt * 8 + (lane >> 2));
    int row = (int)(l * 256 + n);
    int d = (int)(kt * 32 + ks * 16 + (lane & 3) * 2 + reg * 8);
    float v0 = 0.0f, v1 = 0.0f;
    if (d < D1)           v0 = Wl[(size_t)row * D1 + d];
    else if (d == D1)     v0 = bl[row];
    if (d + 1 < D1)       v1 = Wl[(size_t)row * D1 + d + 1];
    else if (d + 1 == D1) v1 = bl[row];
    g_Bp[o] = h2(v0, v1);
}

// ============================================================================
// k_prep1: W_pre fragments (512x512). tile = kt, NW = 16.
// ============================================================================
__global__ void k_prep1(const float* __restrict__ Wp) {
    u32 o = blockIdx.x * 256 + threadIdx.x;   // < 131072
    u32 r = o & 3, lane = (o >> 2) & 31;
    u32 h = (o >> 7) & 1, ks = (o >> 8) & 1, nw = (o >> 9) & 15;
    u32 kt = o >> 13;
    u32 nt = h * 2 + (r >> 1), reg = r & 1;
    int n = (int)(nw * 32 + nt * 8 + (lane >> 2));
    int d = (int)(kt * 32 + ks * 16 + (lane & 3) * 2 + reg * 8);
    g_Bpre[o] = h2(Wp[(size_t)n * DIN + d], Wp[(size_t)n * DIN + d + 1]);
}

// ============================================================================
// k_prep3: right_w fragments (127x513 padded to 128x544). tile = kt, NW = 4.
// ============================================================================
__global__ void k_prep3(const float* __restrict__ rw) {
    u32 o = blockIdx.x * 256 + threadIdx.x;   // < 34816
    u32 r = o & 3, lane = (o >> 2) & 31;
    u32 h = (o >> 7) & 1, ks = (o >> 8) & 1, nw = (o >> 9) & 3;
    u32 kt = o >> 11;
    u32 nt = h * 2 + (r >> 1), reg = r & 1;
    int n = (int)(nw * 32 + nt * 8 + (lane >> 2));
    int d = (int)(kt * 32 + ks * 16 + (lane & 3) * 2 + reg * 8);
    float v0 = (n < NODES && d < D1)     ? rw[(size_t)n * D1 + d]     : 0.0f;
    float v1 = (n < NODES && d + 1 < D1) ? rw[(size_t)n * D1 + d + 1] : 0.0f;
    g_Brw[o] = h2(v0, v1);
}

// ============================================================================
// k0: right_w inverse row norms -- one block (128 thr) per node
// ============================================================================
__global__ void k0_init(const float* __restrict__ right_w) {
    __shared__ float sm[4];
    int n = blockIdx.x, tid = threadIdx.x;
    const float* wr = right_w + (size_t)n * D1;
    float s = 0.0f;
    for (int d = tid; d < D1; d += 128) { float v = wr[d]; s += v * v; }
    #pragma unroll
    for (int o = 16; o > 0; o >>= 1) s += __shfl_xor_sync(0xffffffffu, s, o);
    if ((tid & 31) == 0) sm[tid >> 5] = s;
    __syncthreads();
    if (tid == 0)
        g_invw[n] = 1.0f / fmaxf(sqrtf(sm[0] + sm[1] + sm[2] + sm[3]), 1e-12f);
}

// ============================================================================
// k1: h[:,0:512] = relu(x @ W_pre[0:512]^T + b_pre) -> g_hh pairs 0..255
// ============================================================================
__global__ __launch_bounds__(256, 1) void k1_pre(const float* __restrict__ x,
                                                 const float* __restrict__ bp) {
    int tid = threadIdx.x, wid = tid >> 5, lane = tid & 31;
    int mw = wid >> 2, nwl = wid & 3;
    int m0 = blockIdx.y * 128;
    int nw = blockIdx.x * 4 + nwl;
    int rbase = m0 + mw * 64 + (lane >> 2);

    const u32* Bb = g_Bpre + (size_t)nw * 512 + lane * 4;
    const float* Xb = x + (size_t)rbase * DIN + (lane & 3) * 2;

    float acc[4][4][4];
    #pragma unroll
    for (int a = 0; a < 4; a++)
        #pragma unroll
        for (int b = 0; b < 4; b++)
            #pragma unroll
            for (int c = 0; c < 4; c++) acc[a][b][c] = 0.0f;

    uint4 bb[2][2][2];
    #pragma unroll
    for (int ks = 0; ks < 2; ks++)
        #pragma unroll
        for (int h = 0; h < 2; h++)
            bb[0][ks][h] = __ldg((const uint4*)(Bb + ks * 256 + h * 128));

    #pragma unroll 2
    for (int kt = 0; kt < 16; kt++) {
        int pb = kt & 1, nb = pb ^ 1;
        if (kt + 1 < 16) {
            const u32* t = Bb + (size_t)(kt + 1) * 8192;
            #pragma unroll
            for (int ks = 0; ks < 2; ks++)
                #pragma unroll
                for (int h = 0; h < 2; h++)
                    bb[nb][ks][h] = __ldg((const uint4*)(t + ks * 256 + h * 128));
        }
        u32 av[4][2][2][2];
        #pragma unroll
        for (int mt = 0; mt < 4; mt++)
            #pragma unroll
            for (int rhl = 0; rhl < 2; rhl++)
                #pragma unroll
                for (int ks = 0; ks < 2; ks++)
                    #pragma unroll
                    for (int reg = 0; reg < 2; reg++) {
                        float2 f = *(const float2*)(Xb + (size_t)(mt * 16 + rhl * 8) * DIN
                                                    + kt * 32 + ks * 16 + reg * 8);
                        av[mt][rhl][ks][reg] = h2(f.x, f.y);
                    }
        #pragma unroll
        for (int ks = 0; ks < 2; ks++)
            #pragma unroll
            for (int h = 0; h < 2; h++) {
                uint4 B = bb[pb][ks][h];
                #pragma unroll
                for (int mt = 0; mt < 4; mt++) {
                    mma_f16(acc[mt][h * 2],     av[mt][0][ks][0], av[mt][1][ks][0],
                            av[mt][0][ks][1], av[mt][1][ks][1], B.x, B.y);
                    mma_f16(acc[mt][h * 2 + 1], av[mt][0][ks][0], av[mt][1][ks][0],
                            av[mt][0][ks][1], av[mt][1][ks][1], B.z, B.w);
                }
            }
    }

    int ncol = blockIdx.x * 128 + nwl * 32 + (lane & 3) * 2;
    #pragma unroll
    for (int mt = 0; mt < 4; mt++)
        #pragma unroll
        for (int half = 0; half < 2; half++) {
            int row = rbase + mt * 16 + half * 8;
            #pragma unroll
            for (int nt = 0; nt < 4; nt++) {
                int n = ncol + nt * 8;
                float v0 = fmaxf(acc[mt][nt][half * 2]     + __ldg(bp + n),     0.0f);
                float v1 = fmaxf(acc[mt][nt][half * 2 + 1] + __ldg(bp + n + 1), 0.0f);
                g_hh[(size_t)row * HP + (n >> 1)] = h2(v0, v1);
            }
        }
}

// ============================================================================
// k1b2: h[:,512] dot + pad writes + row inverse-norm (merged).
// One warp per row.
// ============================================================================
__global__ void k1b2(const float* __restrict__ x, const float* __restrict__ Wp,
                     const float* __restrict__ bp) {
    int w = threadIdx.x >> 5, lane = threadIdx.x & 31;
    int b = blockIdx.x * 8 + w;
    const float* xr = x + (size_t)b * DIN;
    const float* wr = Wp + (size_t)512 * DIN;
    float s = 0.0f;
    #pragma unroll 4
    for (int d = lane; d < DIN; d += 32) s += xr[d] * wr[d];
    #pragma unroll
    for (int o = 16; o > 0; o >>= 1) s += __shfl_xor_sync(0xffffffffu, s, o);
    float h512 = fmaxf(s + __ldg(bp + 512), 0.0f);   // uniform across warp

    u32* row = g_hh + (size_t)b * HP;
    if (lane == 0) row[256] = h2(h512, 1.0f);
    else if (lane < 16) row[256 + lane] = 0u;

    float t = 0.0f;
    for (int i = lane; i < 256; i += 32) {
        float2 f = h2f(row[i]);
        t += f.x * f.x + f.y * f.y;
    }
    #pragma unroll
    for (int o = 16; o > 0; o >>= 1) t += __shfl_xor_sync(0xffffffffu, t, o);
    if (lane == 0) g_invh[b] = 1.0f / fmaxf(sqrtf(t + h512 * h512), 1e-12f);
}

// ============================================================================
// k3: right[b,n] = invh[b]*invw[n]*(h . right_w[n])  -- fp16 mma
// ============================================================================
__global__ __launch_bounds__(256, 1) void k3_right() {
    int tid = threadIdx.x, wid = tid >> 5, lane = tid & 31;
    int mw = wid >> 2, nwl = wid & 3;
    int m0 = blockIdx.y * 128;
    int rbase = m0 + mw * 64 + (lane >> 2);

    const u32* Bb = g_Brw + (size_t)nwl * 512 + lane * 4;
    const u32* Hb = g_hh + (size_t)rbase * HP + (lane & 3);

    float acc[4][4][4];
    #pragma unroll
    for (int a = 0; a < 4; a++)
        #pragma unroll
        for (int b = 0; b < 4; b++)
            #pragma unroll
            for (int c = 0; c < 4; c++) acc[a][b][c] = 0.0f;

    #pragma unroll 1
    for (int kt = 0; kt < 17; kt++) {
        uint4 bb[2][2];
        #pragma unroll
        for (int ks = 0; ks < 2; ks++)
            #pragma unroll
            for (int h = 0; h < 2; h++)
                bb[ks][h] = __ldg((const uint4*)(Bb + (size_t)kt * 2048 + ks * 256 + h * 128));
        u32 hv[4][2][2][2];
        #pragma unroll
        for (int mt = 0; mt < 4; mt++)
            #pragma unroll
            for (int rhl = 0; rhl < 2; rhl++)
                #pragma unroll
                for (int ks = 0; ks < 2; ks++)
                    #pragma unroll
                    for (int reg = 0; reg < 2; reg++)
                        hv[mt][rhl][ks][reg] = __ldg(Hb + (size_t)(mt * 16 + rhl * 8) * HP
                                                     + kt * 16 + ks * 8 + reg * 4);
        #pragma unroll
        for (int ks = 0; ks < 2; ks++)
            #pragma unroll
            for (int h = 0; h < 2; h++) {
                uint4 B = bb[ks][h];
                #pragma unroll
                for (int mt = 0; mt < 4; mt++) {
                    mma_f16(acc[mt][h * 2],     hv[mt][0][ks][0], hv[mt][1][ks][0],
                            hv[mt][0][ks][1], hv[mt][1][ks][1], B.x, B.y);
                    mma_f16(acc[mt][h * 2 + 1], hv[mt][0][ks][0], hv[mt][1][ks][0],
                            hv[mt][0][ks][1], hv[mt][1][ks][1], B.z, B.w);
                }
            }
    }

    #pragma unroll
    for (int mt = 0; mt < 4; mt++)
        #pragma unroll
        for (int half = 0; half < 2; half++) {
            int row = rbase + mt * 16 + half * 8;
            float ih = g_invh[row];
            #pragma unroll
            for (int nt = 0; nt < 4; nt++) {
                int n = nwl * 32 + nt * 8 + (lane & 3) * 2;
                if (n < NODES)
                    g_right[(size_t)row * 128 + n] = acc[mt][nt][half * 2] * ih * g_invw[n];
                if (n + 1 < NODES)
                    g_right[(size_t)row * 128 + n + 1] = acc[mt][nt][half * 2 + 1] * ih * g_invw[n + 1];
            }
        }
}

// ============================================================================
// k4: routing -> g_swh2 (packed (s,s) half2, [l][b]), entropy partials
// ============================================================================
__global__ __launch_bounds__(256) void k4_route(const int* __restrict__ ridx,
                                                const int* __restrict__ rside) {
    __shared__ int s_idx[LEAVES * 7];
    __shared__ int s_side[LEAVES * 7];
    __shared__ float s_lr[8][128];
    __shared__ float s_ll[8][128];
    __shared__ float s_ent[8];

    int tid = threadIdx.x;
    for (int t = tid; t < LEAVES * 7; t += 256) { s_idx[t] = ridx[t]; s_side[t] = rside[t]; }
    __syncthreads();

    int w = tid / 32, lane = tid % 32;
    int b = blockIdx.x * 8 + w;

    for (int n = lane; n < NODES; n += 32) {
        float r = g_right[b * 128 + n];
        float rd = 0.5f * (1.0f - r);
        float ld = 0.5f * (1.0f + r);
        s_lr[w][n] = logf(fminf(fmaxf(rd, 0.01f), 0.99f));
        s_ll[w][n] = logf(fminf(fmaxf(ld, 0.01f), 0.99f));
    }
    __syncwarp();

    float ent = 0.0f;
    for (int li = lane; li < LEAVES; li += 32) {
        float lp = 0.0f;
        #pragma unroll
        for (int j = 0; j < 7; j++) {
            int node = s_idx[li * 7 + j];
            int side = s_side[li * 7 + j];
            lp += side ? s_ll[w][node] : s_lr[w][node];
        }
        float s = expf(lp);
        g_swh2[li * BATCH + b] = h2(s, s);
        ent -= s * lp;
    }
    #pragma unroll
    for (int o = 16; o > 0; o >>= 1) ent += __shfl_xor_sync(0xffffffffu, ent, o);
    if (lane == 0) s_ent[w] = ent;
    __syncthreads();
    if (tid == 0) {
        float t = 0.0f;
        #pragma unroll
        for (int i = 0; i < 8; i++) t += s_ent[i];
        g_entpart[blockIdx.x] = t;
    }
}

// ============================================================================
// k5: deterministic entropy reduction -> scale scalar
// ============================================================================
__global__ void k5_scale() {
    __shared__ float sm[256];
    float s = 0.0f;
    for (int i = threadIdx.x; i < 1024; i += 256) s += g_entpart[i];
    sm[threadIdx.x] = s;
    __syncthreads();
    for (int st = 128; st > 0; st >>= 1) {
        if (threadIdx.x < st) sm[threadIdx.x] += sm[threadIdx.x + st];
        __syncthreads();
    }
    if (threadIdx.x == 0) {
        float max_ent = (128.0f / 6.0f) * logf(6.0f);
        g_scale = 1.0f + (sm[0] / (float)BATCH) / max_ent;
    }
}

// ============================================================================
// k6: fp16 mma leaf contraction, no smem, no barriers (R5 structure).
// grid (2 n-halves, 64 m-tiles), 8 warps, warp tile 64m x 32n.
// A = HMUL2(h_frag, sw2); B direct LDG.128 with 1-deep register prefetch.
// ============================================================================
__global__ __launch_bounds__(256, 1) void k6_mma(float* __restrict__ out) {
    int tid = threadIdx.x, wid = tid >> 5, lane = tid & 31;
    int mw = wid >> 2, nwl = wid & 3;
    int m0 = blockIdx.y * 128;
    int nw = blockIdx.x * 4 + nwl;
    int rbase = m0 + mw * 64 + (lane >> 2);

    const u32* Bb = g_Bp + (size_t)nw * 512 + lane * 4;     // + tile*4096 (+ks*256+h*128)
    const u32* SWb = g_swh2 + rbase;
    const u32* Hb = g_hh + (size_t)rbase * HP + (lane & 3);

    float acc[4][4][4];
    #pragma unroll
    for (int a = 0; a < 4; a++)
        #pragma unroll
        for (int b = 0; b < 4; b++)
            #pragma unroll
            for (int c = 0; c < 4; c++) acc[a][b][c] = 0.0f;

    uint4 bb[2][2][2];       // [buf][ks][h]
    u32 sw[2][8];            // [buf][mt*2 + rhl]
    u32 hv[4][2][2][2];      // [mt][rhl][ks][reg]

    // preload it=0 (kt=0, l=0)
    #pragma unroll
    for (int ks = 0; ks < 2; ks++)
        #pragma unroll
        for (int h = 0; h < 2; h++)
            bb[0][ks][h] = __ldg((const uint4*)(Bb + ks * 256 + h * 128));
    #pragma unroll
    for (int j = 0; j < 8; j++)
        sw[0][j] = __ldg(SWb + (j >> 1) * 16 + (j & 1) * 8);

    int it = 0;
    #pragma unroll 1
    for (int kt = 0; kt < NKT; kt++) {
        #pragma unroll
        for (int mt = 0; mt < 4; mt++)
            #pragma unroll
            for (int rhl = 0; rhl < 2; rhl++)
                #pragma unroll
                for (int ks = 0; ks < 2; ks++)
                    #pragma unroll
                    for (int reg = 0; reg < 2; reg++)
                        hv[mt][rhl][ks][reg] = __ldg(Hb + (size_t)(mt * 16 + rhl * 8) * HP
                                                     + kt * 16 + ks * 8 + reg * 4);
        #pragma unroll 2
        for (int l = 0; l < LEAVES; l++) {
            int pb = l & 1, nb = pb ^ 1;
            int nit = it + 1;
            if (nit < ITERS) {
                int nl = nit & 127, nkt = nit >> 7;
                const u32* t = Bb + (size_t)(nl * 17 + nkt) * 4096;
                #pragma unroll
                for (int ks = 0; ks < 2; ks++)
                    #pragma unroll
                    for (int h = 0; h < 2; h++)
                        bb[nb][ks][h] = __ldg((const uint4*)(t + ks * 256 + h * 128));
                const u32* sp = SWb + (size_t)nl * BATCH;
                #pragma unroll
                for (int j = 0; j < 8; j++)
                    sw[nb][j] = __ldg(sp + (j >> 1) * 16 + (j & 1) * 8);
            }
            #pragma unroll
            for (int ks = 0; ks < 2; ks++) {
                u32 A0[4], A1[4], A2[4], A3[4];
                #pragma unroll
                for (int mt = 0; mt < 4; mt++) {
                    A0[mt] = hmul2(hv[mt][0][ks][0], sw[pb][mt * 2]);
                    A1[mt] = hmul2(hv[mt][1][ks][0], sw[pb][mt * 2 + 1]);
                    A2[mt] = hmul2(hv[mt][0][ks][1], sw[pb][mt * 2]);
                    A3[mt] = hmul2(hv[mt][1][ks][1], sw[pb][mt * 2 + 1]);
                }
                #pragma unroll
                for (int h = 0; h < 2; h++) {
                    uint4 B = bb[pb][ks][h];
                    #pragma unroll
                    for (int mt = 0; mt < 4; mt++) {
                        mma_f16(acc[mt][h * 2],     A0[mt], A1[mt], A2[mt], A3[mt], B.x, B.y);
                        mma_f16(acc[mt][h * 2 + 1], A0[mt], A1[mt], A2[mt], A3[mt], B.z, B.w);
                    }
                }
            }
            it++;
        }
    }

    float sc = g_scale;
    int ncol = blockIdx.x * 128 + nwl * 32 + (lane & 3) * 2;
    #pragma unroll
    for (int mt = 0; mt < 4; mt++)
        #pragma unroll
        for (int half = 0; half < 2; half++) {
            int row = rbase + mt * 16 + half * 8;
            float* op = out + (size_t)row * DOUT + ncol;
            #pragma unroll
            for (int nt = 0; nt < 4; nt++) {
                float2 v;
                v.x = acc[mt][nt][half * 2] * sc;
                v.y = acc[mt][nt][half * 2 + 1] * sc;
                *(float2*)(op + nt * 8) = v;
            }
        }
}

// ============================================================================
extern "C" void kernel_launch(void* const* d_in, const int* in_sizes, int n_in,
                              void* d_out, int out_size) {
    const float* x      = (const float*)d_in[0];
    const float* W_pre  = (const float*)d_in[1];
    const float* b_pre  = (const float*)d_in[2];
    const float* rw     = (const float*)d_in[3];
    const float* W_leaf = (const float*)d_in[4];
    const float* b_leaf = (const float*)d_in[5];
    const int*   ridx   = (const int*)d_in[6];
    const int*   rside  = (const int*)d_in[7];
    float* out = (float*)d_out;

    k_prep<<<34816, 256>>>(W_leaf, b_leaf);
    k_prep1<<<512, 256>>>(W_pre);
    k_prep3<<<136, 256>>>(rw);
    k0_init<<<NODES, 128>>>(rw);
    k1_pre<<<dim3(4, 64), 256>>>(x, b_pre);
    k1b2<<<1024, 256>>>(x, W_pre, b_pre);
    k3_right<<<dim3(1, 64), 256>>>();
    k4_route<<<1024, 256>>>(ridx, rside);
    k5_scale<<<1, 256>>>();
    k6_mma<<<dim3(2, 64), 256>>>(out);
}

// round 8
// speedup vs baseline: 1.7814x; 1.1366x over previous
#include <cuda_runtime.h>
#include <cuda_fp16.h>
#include <math.h>

// ---------------------------------------------------------------------------
// DTree forward. Round 8: k6 re-gridded to 256 CTAs x 128 thr (warp tile
// 64m x 32n, one warp per n-slice -> no duplicate B loads; m-tile 64 ->
// identical total L2 traffic, 148/148 SM fill). Scale reduction folded into
// k6 epilogue; all weight-prep kernels fused into one launch.
// Launch order puts k6 at index 5 = ncu capture slot.
// ---------------------------------------------------------------------------

#define BATCH   8192
#define DIN     512
#define D1      513
#define HP      272      // g_hh row stride in u32 (half2 pairs): 544 halves
#define NKT     17
#define NODES   127
#define LEAVES  128
#define DOUT    256
#define ITERS   (NKT * LEAVES)   // 2176

// prep_all block ranges
#define PB_LEAF 34816
#define PB_PRE  512
#define PB_RW   136
#define PB_NORM NODES

typedef unsigned long long u64;
typedef unsigned int u32;

// -------------------- scratch (device globals; no allocation) --------------
__device__ __align__(16) u32 g_hh[BATCH * HP];          // 8.9 MB packed half2 h
__device__ __align__(16) u32 g_Bp[LEAVES * NKT * 4096]; // 35.7 MB leaf B fragments
__device__ __align__(16) u32 g_Bpre[16 * 8192];         // 0.52 MB W_pre fragments
__device__ __align__(16) u32 g_Brw[NKT * 2048];         // 0.14 MB right_w fragments
__device__ u32 g_swh2[LEAVES * BATCH];                  // 4.2 MB (s,s) half2
__device__ float g_right[BATCH * 128];
__device__ float g_invh[BATCH];
__device__ float g_invw[NODES];
__device__ float g_entpart[1024];

// -------------------- helpers ----------------------------------------------
__device__ __forceinline__ u32 h2(float lo, float hi) {
    u32 r; asm("cvt.rn.f16x2.f32 %0, %1, %2;" : "=r"(r) : "f"(hi), "f"(lo)); return r;
}
__device__ __forceinline__ u32 hmul2(u32 a, u32 b) {
    u32 r; asm("mul.f16x2 %0, %1, %2;" : "=r"(r) : "r"(a), "r"(b)); return r;
}
__device__ __forceinline__ float2 h2f(u32 v) {
    __half2 h = *reinterpret_cast<__half2*>(&v);
    return __half22float2(h);
}
__device__ __forceinline__ void mma_f16(float* c, u32 a0, u32 a1, u32 a2, u32 a3,
                                        u32 b0, u32 b1) {
    asm volatile("mma.sync.aligned.m16n8k16.row.col.f32.f16.f16.f32 "
                 "{%0,%1,%2,%3}, {%4,%5,%6,%7}, {%8,%9}, {%0,%1,%2,%3};"
                 : "+f"(c[0]), "+f"(c[1]), "+f"(c[2]), "+f"(c[3])
                 : "r"(a0), "r"(a1), "r"(a2), "r"(a3), "r"(b0), "r"(b1));
}

// Fragment addressing convention (m16n8k16):
//   B frag u32 index = (((tile*NW + nw)*2 + ks)*2 + h)*128 + lane*4 + r
//   nt = h*2 + (r>>1); reg = r&1
//   n  = nw*32 + nt*8 + (lane>>2)
//   d  = kt*32 + ks*16 + (lane&3)*2 + reg*8   (value = half2(W[n][d], W[n][d+1]))

// ============================================================================
// k_prep_all: all weight preprocessing in one launch.
//   blocks [0, PB_LEAF)                    : leaf B fragments (tile=l*17+kt, NW=8)
//   blocks [PB_LEAF, +PB_PRE)              : W_pre fragments (tile=kt, NW=16)
//   blocks [.., +PB_RW)                    : right_w fragments (tile=kt, NW=4)
//   blocks [.., +PB_NORM)                  : right_w inverse row norms
// ============================================================================
__global__ void k_prep_all(const float* __restrict__ Wl, const float* __restrict__ bl,
                           const float* __restrict__ Wp, const float* __restrict__ rw) {
    int blk = blockIdx.x;
    if (blk < PB_LEAF) {
        u32 o = (u32)blk * 256 + threadIdx.x;
        u32 r = o & 3, lane = (o >> 2) & 31;
        u32 h = (o >> 7) & 1, ks = (o >> 8) & 1, nw = (o >> 9) & 7;
        u32 t = o >> 12;
        u32 kt = t % 17, l = t / 17;
        u32 nt = h * 2 + (r >> 1), reg = r & 1;
        int n = (int)(nw * 32 + nt * 8 + (lane >> 2));
        int row = (int)(l * 256 + n);
        int d = (int)(kt * 32 + ks * 16 + (lane & 3) * 2 + reg * 8);
        float v0 = 0.0f, v1 = 0.0f;
        if (d < D1)           v0 = Wl[(size_t)row * D1 + d];
        else if (d == D1)     v0 = bl[row];
        if (d + 1 < D1)       v1 = Wl[(size_t)row * D1 + d + 1];
        else if (d + 1 == D1) v1 = bl[row];
        g_Bp[o] = h2(v0, v1);
        return;
    }
    blk -= PB_LEAF;
    if (blk < PB_PRE) {
        u32 o = (u32)blk * 256 + threadIdx.x;   // < 131072
        u32 r = o & 3, lane = (o >> 2) & 31;
        u32 h = (o >> 7) & 1, ks = (o >> 8) & 1, nw = (o >> 9) & 15;
        u32 kt = o >> 13;
        u32 nt = h * 2 + (r >> 1), reg = r & 1;
        int n = (int)(nw * 32 + nt * 8 + (lane >> 2));
        int d = (int)(kt * 32 + ks * 16 + (lane & 3) * 2 + reg * 8);
        g_Bpre[o] = h2(Wp[(size_t)n * DIN + d], Wp[(size_t)n * DIN + d + 1]);
        return;
    }
    blk -= PB_PRE;
    if (blk < PB_RW) {
        u32 o = (u32)blk * 256 + threadIdx.x;   // < 34816
        u32 r = o & 3, lane = (o >> 2) & 31;
        u32 h = (o >> 7) & 1, ks = (o >> 8) & 1, nw = (o >> 9) & 3;
        u32 kt = o >> 11;
        u32 nt = h * 2 + (r >> 1), reg = r & 1;
        int n = (int)(nw * 32 + nt * 8 + (lane >> 2));
        int d = (int)(kt * 32 + ks * 16 + (lane & 3) * 2 + reg * 8);
        float v0 = (n < NODES && d < D1)     ? rw[(size_t)n * D1 + d]     : 0.0f;
        float v1 = (n < NODES && d + 1 < D1) ? rw[(size_t)n * D1 + d + 1] : 0.0f;
        g_Brw[o] = h2(v0, v1);
        return;
    }
    blk -= PB_RW;
    {   // inverse row norm for node blk
        __shared__ float sm[8];
        int n = blk, tid = threadIdx.x;
        const float* wr = rw + (size_t)n * D1;
        float s = 0.0f;
        for (int d = tid; d < D1; d += 256) { float v = wr[d]; s += v * v; }
        #pragma unroll
        for (int o = 16; o > 0; o >>= 1) s += __shfl_xor_sync(0xffffffffu, s, o);
        if ((tid & 31) == 0) sm[tid >> 5] = s;
        __syncthreads();
        if (tid == 0) {
            float t = 0.0f;
            #pragma unroll
            for (int i = 0; i < 8; i++) t += sm[i];
            g_invw[n] = 1.0f / fmaxf(sqrtf(t), 1e-12f);
        }
    }
}

// ============================================================================
// k1: h[:,0:512] = relu(x @ W_pre[0:512]^T + b_pre) -> g_hh pairs 0..255
// ============================================================================
__global__ __launch_bounds__(256, 1) void k1_pre(const float* __restrict__ x,
                                                 const float* __restrict__ bp) {
    int tid = threadIdx.x, wid = tid >> 5, lane = tid & 31;
    int mw = wid >> 2, nwl = wid & 3;
    int m0 = blockIdx.y * 128;
    int nw = blockIdx.x * 4 + nwl;
    int rbase = m0 + mw * 64 + (lane >> 2);

    const u32* Bb = g_Bpre + (size_t)nw * 512 + lane * 4;
    const float* Xb = x + (size_t)rbase * DIN + (lane & 3) * 2;

    float acc[4][4][4];
    #pragma unroll
    for (int a = 0; a < 4; a++)
        #pragma unroll
        for (int b = 0; b < 4; b++)
            #pragma unroll
            for (int c = 0; c < 4; c++) acc[a][b][c] = 0.0f;

    uint4 bb[2][2][2];
    #pragma unroll
    for (int ks = 0; ks < 2; ks++)
        #pragma unroll
        for (int h = 0; h < 2; h++)
            bb[0][ks][h] = __ldg((const uint4*)(Bb + ks * 256 + h * 128));

    #pragma unroll 2
    for (int kt = 0; kt < 16; kt++) {
        int pb = kt & 1, nb = pb ^ 1;
        if (kt + 1 < 16) {
            const u32* t = Bb + (size_t)(kt + 1) * 8192;
            #pragma unroll
            for (int ks = 0; ks < 2; ks++)
                #pragma unroll
                for (int h = 0; h < 2; h++)
                    bb[nb][ks][h] = __ldg((const uint4*)(t + ks * 256 + h * 128));
        }
        u32 av[4][2][2][2];
        #pragma unroll
        for (int mt = 0; mt < 4; mt++)
            #pragma unroll
            for (int rhl = 0; rhl < 2; rhl++)
                #pragma unroll
                for (int ks = 0; ks < 2; ks++)
                    #pragma unroll
                    for (int reg = 0; reg < 2; reg++) {
                        float2 f = *(const float2*)(Xb + (size_t)(mt * 16 + rhl * 8) * DIN
                                                    + kt * 32 + ks * 16 + reg * 8);
                        av[mt][rhl][ks][reg] = h2(f.x, f.y);
                    }
        #pragma unroll
        for (int ks = 0; ks < 2; ks++)
            #pragma unroll
            for (int h = 0; h < 2; h++) {
                uint4 B = bb[pb][ks][h];
                #pragma unroll
                for (int mt = 0; mt < 4; mt++) {
                    mma_f16(acc[mt][h * 2],     av[mt][0][ks][0], av[mt][1][ks][0],
                            av[mt][0][ks][1], av[mt][1][ks][1], B.x, B.y);
                    mma_f16(acc[mt][h * 2 + 1], av[mt][0][ks][0], av[mt][1][ks][0],
                            av[mt][0][ks][1], av[mt][1][ks][1], B.z, B.w);
                }
            }
    }

    int ncol = blockIdx.x * 128 + nwl * 32 + (lane & 3) * 2;
    #pragma unroll
    for (int mt = 0; mt < 4; mt++)
        #pragma unroll
        for (int half = 0; half < 2; half++) {
            int row = rbase + mt * 16 + half * 8;
            #pragma unroll
            for (int nt = 0; nt < 4; nt++) {
                int n = ncol + nt * 8;
                float v0 = fmaxf(acc[mt][nt][half * 2]     + __ldg(bp + n),     0.0f);
                float v1 = fmaxf(acc[mt][nt][half * 2 + 1] + __ldg(bp + n + 1), 0.0f);
                g_hh[(size_t)row * HP + (n >> 1)] = h2(v0, v1);
            }
        }
}

// ============================================================================
// k1b2: h[:,512] dot + pad writes + row inverse-norm. One warp per row.
// ============================================================================
__global__ void k1b2(const float* __restrict__ x, const float* __restrict__ Wp,
                     const float* __restrict__ bp) {
    int w = threadIdx.x >> 5, lane = threadIdx.x & 31;
    int b = blockIdx.x * 8 + w;
    const float* xr = x + (size_t)b * DIN;
    const float* wr = Wp + (size_t)512 * DIN;
    float s = 0.0f;
    #pragma unroll 4
    for (int d = lane; d < DIN; d += 32) s += xr[d] * wr[d];
    #pragma unroll
    for (int o = 16; o > 0; o >>= 1) s += __shfl_xor_sync(0xffffffffu, s, o);
    float h512 = fmaxf(s + __ldg(bp + 512), 0.0f);   // uniform across warp

    u32* row = g_hh + (size_t)b * HP;
    if (lane == 0) row[256] = h2(h512, 1.0f);
    else if (lane < 16) row[256 + lane] = 0u;

    float t = 0.0f;
    for (int i = lane; i < 256; i += 32) {
        float2 f = h2f(row[i]);
        t += f.x * f.x + f.y * f.y;
    }
    #pragma unroll
    for (int o = 16; o > 0; o >>= 1) t += __shfl_xor_sync(0xffffffffu, t, o);
    if (lane == 0) g_invh[b] = 1.0f / fmaxf(sqrtf(t + h512 * h512), 1e-12f);
}

// ============================================================================
// k3: right[b,n] = invh[b]*invw[n]*(h . right_w[n])  -- fp16 mma
// ============================================================================
__global__ __launch_bounds__(256, 1) void k3_right() {
    int tid = threadIdx.x, wid = tid >> 5, lane = tid & 31;
    int mw = wid >> 2, nwl = wid & 3;
    int m0 = blockIdx.y * 128;
    int rbase = m0 + mw * 64 + (lane >> 2);

    const u32* Bb = g_Brw + (size_t)nwl * 512 + lane * 4;
    const u32* Hb = g_hh + (size_t)rbase * HP + (lane & 3);

    float acc[4][4][4];
    #pragma unroll
    for (int a = 0; a < 4; a++)
        #pragma unroll
        for (int b = 0; b < 4; b++)
            #pragma unroll
            for (int c = 0; c < 4; c++) acc[a][b][c] = 0.0f;

    #pragma unroll 1
    for (int kt = 0; kt < 17; kt++) {
        uint4 bb[2][2];
        #pragma unroll
        for (int ks = 0; ks < 2; ks++)
            #pragma unroll
            for (int h = 0; h < 2; h++)
                bb[ks][h] = __ldg((const uint4*)(Bb + (size_t)kt * 2048 + ks * 256 + h * 128));
        u32 hv[4][2][2][2];
        #pragma unroll
        for (int mt = 0; mt < 4; mt++)
            #pragma unroll
            for (int rhl = 0; rhl < 2; rhl++)
                #pragma unroll
                for (int ks = 0; ks < 2; ks++)
                    #pragma unroll
                    for (int reg = 0; reg < 2; reg++)
                        hv[mt][rhl][ks][reg] = __ldg(Hb + (size_t)(mt * 16 + rhl * 8) * HP
                                                     + kt * 16 + ks * 8 + reg * 4);
        #pragma unroll
        for (int ks = 0; ks < 2; ks++)
            #pragma unroll
            for (int h = 0; h < 2; h++) {
                uint4 B = bb[ks][h];
                #pragma unroll
                for (int mt = 0; mt < 4; mt++) {
                    mma_f16(acc[mt][h * 2],     hv[mt][0][ks][0], hv[mt][1][ks][0],
                            hv[mt][0][ks][1], hv[mt][1][ks][1], B.x, B.y);
                    mma_f16(acc[mt][h * 2 + 1], hv[mt][0][ks][0], hv[mt][1][ks][0],
                            hv[mt][0][ks][1], hv[mt][1][ks][1], B.z, B.w);
                }
            }
    }

    #pragma unroll
    for (int mt = 0; mt < 4; mt++)
        #pragma unroll
        for (int half = 0; half < 2; half++) {
            int row = rbase + mt * 16 + half * 8;
            float ih = g_invh[row];
            #pragma unroll
            for (int nt = 0; nt < 4; nt++) {
                int n = nwl * 32 + nt * 8 + (lane & 3) * 2;
                if (n < NODES)
                    g_right[(size_t)row * 128 + n] = acc[mt][nt][half * 2] * ih * g_invw[n];
                if (n + 1 < NODES)
                    g_right[(size_t)row * 128 + n + 1] = acc[mt][nt][half * 2 + 1] * ih * g_invw[n + 1];
            }
        }
}

// ============================================================================
// k4: routing -> g_swh2 (packed (s,s) half2, [l][b]), entropy partials
// ============================================================================
__global__ __launch_bounds__(256) void k4_route(const int* __restrict__ ridx,
                                                const int* __restrict__ rside) {
    __shared__ int s_idx[LEAVES * 7];
    __shared__ int s_side[LEAVES * 7];
    __shared__ float s_lr[8][128];
    __shared__ float s_ll[8][128];
    __shared__ float s_ent[8];

    int tid = threadIdx.x;
    for (int t = tid; t < LEAVES * 7; t += 256) { s_idx[t] = ridx[t]; s_side[t] = rside[t]; }
    __syncthreads();

    int w = tid / 32, lane = tid % 32;
    int b = blockIdx.x * 8 + w;

    for (int n = lane; n < NODES; n += 32) {
        float r = g_right[b * 128 + n];
        float rd = 0.5f * (1.0f - r);
        float ld = 0.5f * (1.0f + r);
        s_lr[w][n] = logf(fminf(fmaxf(rd, 0.01f), 0.99f));
        s_ll[w][n] = logf(fminf(fmaxf(ld, 0.01f), 0.99f));
    }
    __syncwarp();

    float ent = 0.0f;
    for (int li = lane; li < LEAVES; li += 32) {
        float lp = 0.0f;
        #pragma unroll
        for (int j = 0; j < 7; j++) {
            int node = s_idx[li * 7 + j];
            int side = s_side[li * 7 + j];
            lp += side ? s_ll[w][node] : s_lr[w][node];
        }
        float s = expf(lp);
        g_swh2[li * BATCH + b] = h2(s, s);
        ent -= s * lp;
    }
    #pragma unroll
    for (int o = 16; o > 0; o >>= 1) ent += __shfl_xor_sync(0xffffffffu, ent, o);
    if (lane == 0) s_ent[w] = ent;
    __syncthreads();
    if (tid == 0) {
        float t = 0.0f;
        #pragma unroll
        for (int i = 0; i < 8; i++) t += s_ent[i];
        g_entpart[blockIdx.x] = t;
    }
}

// ============================================================================
// k6: fp16 mma leaf contraction. 256 CTAs x 128 thr (4 warps, one per nwl),
// warp tile 64m x 32n, CTA tile 64m x 128n, 2 CTAs/SM -> one wave on 148 SMs.
// No duplicate B loads (each warp owns a distinct n-slice). Scale reduction
// from g_entpart computed inline in the epilogue (deterministic).
// ============================================================================
__global__ __launch_bounds__(128, 2) void k6_mma(float* __restrict__ out) {
    int tid = threadIdx.x, wid = tid >> 5, lane = tid & 31;
    int m0 = blockIdx.y * 64;
    int nw = blockIdx.x * 4 + wid;
    int rbase = m0 + (lane >> 2);

    const u32* Bb = g_Bp + (size_t)nw * 512 + lane * 4;     // + tile*4096 (+ks*256+h*128)
    const u32* SWb = g_swh2 + rbase;
    const u32* Hb = g_hh + (size_t)rbase * HP + (lane & 3);

    float acc[4][4][4];
    #pragma unroll
    for (int a = 0; a < 4; a++)
        #pragma unroll
        for (int b = 0; b < 4; b++)
            #pragma unroll
            for (int c = 0; c < 4; c++) acc[a][b][c] = 0.0f;

    uint4 bb[2][2][2];       // [buf][ks][h]
    u32 sw[2][8];            // [buf][mt*2 + rhl]
    u32 hv[4][2][2][2];      // [mt][rhl][ks][reg]

    // preload it=0 (kt=0, l=0)
    #pragma unroll
    for (int ks = 0; ks < 2; ks++)
        #pragma unroll
        for (int h = 0; h < 2; h++)
            bb[0][ks][h] = __ldg((const uint4*)(Bb + ks * 256 + h * 128));
    #pragma unroll
    for (int j = 0; j < 8; j++)
        sw[0][j] = __ldg(SWb + (j >> 1) * 16 + (j & 1) * 8);

    int it = 0;
    #pragma unroll 1
    for (int kt = 0; kt < NKT; kt++) {
        #pragma unroll
        for (int mt = 0; mt < 4; mt++)
            #pragma unroll
            for (int rhl = 0; rhl < 2; rhl++)
                #pragma unroll
                for (int ks = 0; ks < 2; ks++)
                    #pragma unroll
                    for (int reg = 0; reg < 2; reg++)
                        hv[mt][rhl][ks][reg] = __ldg(Hb + (size_t)(mt * 16 + rhl * 8) * HP
                                                     + kt * 16 + ks * 8 + reg * 4);
        #pragma unroll 2
        for (int l = 0; l < LEAVES; l++) {
            int pb = l & 1, nb = pb ^ 1;
            int nit = it + 1;
            if (nit < ITERS) {
                int nl = nit & 127, nkt = nit >> 7;
                const u32* t = Bb + (size_t)(nl * 17 + nkt) * 4096;
                #pragma unroll
                for (int ks = 0; ks < 2; ks++)
                    #pragma unroll
                    for (int h = 0; h < 2; h++)
                        bb[nb][ks][h] = __ldg((const uint4*)(t + ks * 256 + h * 128));
                const u32* sp = SWb + (size_t)nl * BATCH;
                #pragma unroll
                for (int j = 0; j < 8; j++)
                    sw[nb][j] = __ldg(sp + (j >> 1) * 16 + (j & 1) * 8);
            }
            #pragma unroll
            for (int ks = 0; ks < 2; ks++) {
                u32 A0[4], A1[4], A2[4], A3[4];
                #pragma unroll
                for (int mt = 0; mt < 4; mt++) {
                    A0[mt] = hmul2(hv[mt][0][ks][0], sw[pb][mt * 2]);
                    A1[mt] = hmul2(hv[mt][1][ks][0], sw[pb][mt * 2 + 1]);
                    A2[mt] = hmul2(hv[mt][0][ks][1], sw[pb][mt * 2]);
                    A3[mt] = hmul2(hv[mt][1][ks][1], sw[pb][mt * 2 + 1]);
                }
                #pragma unroll
                for (int h = 0; h < 2; h++) {
                    uint4 B = bb[pb][ks][h];
                    #pragma unroll
                    for (int mt = 0; mt < 4; mt++) {
                        mma_f16(acc[mt][h * 2],     A0[mt], A1[mt], A2[mt], A3[mt], B.x, B.y);
                        mma_f16(acc[mt][h * 2 + 1], A0[mt], A1[mt], A2[mt], A3[mt], B.z, B.w);
                    }
                }
            }
            it++;
        }
    }

    // inline deterministic scale = 1 + (sum(entpart)/BATCH)/max_ent
    __shared__ float sm[128];
    {
        float s = 0.0f;
        #pragma unroll
        for (int i = 0; i < 8; i++) s += g_entpart[tid + i * 128];
        sm[tid] = s;
    }
    __syncthreads();
    #pragma unroll
    for (int st = 64; st > 0; st >>= 1) {
        if (tid < st) sm[tid] += sm[tid + st];
        __syncthreads();
    }
    float max_ent = (128.0f / 6.0f) * logf(6.0f);
    float sc = 1.0f + (sm[0] / (float)BATCH) / max_ent;

    int ncol = blockIdx.x * 128 + wid * 32 + (lane & 3) * 2;
    #pragma unroll
    for (int mt = 0; mt < 4; mt++)
        #pragma unroll
        for (int half = 0; half < 2; half++) {
            int row = rbase + mt * 16 + half * 8;
            float* op = out + (size_t)row * DOUT + ncol;
            #pragma unroll
            for (int nt = 0; nt < 4; nt++) {
                float2 v;
                v.x = acc[mt][nt][half * 2] * sc;
                v.y = acc[mt][nt][half * 2 + 1] * sc;
                *(float2*)(op + nt * 8) = v;
            }
        }
}

// ============================================================================
extern "C" void kernel_launch(void* const* d_in, const int* in_sizes, int n_in,
                              void* d_out, int out_size) {
    const float* x      = (const float*)d_in[0];
    const float* W_pre  = (const float*)d_in[1];
    const float* b_pre  = (const float*)d_in[2];
    const float* rw     = (const float*)d_in[3];
    const float* W_leaf = (const float*)d_in[4];
    const float* b_leaf = (const float*)d_in[5];
    const int*   ridx   = (const int*)d_in[6];
    const int*   rside  = (const int*)d_in[7];
    float* out = (float*)d_out;

    k_prep_all<<<PB_LEAF + PB_PRE + PB_RW + PB_NORM, 256>>>(W_leaf, b_leaf, W_pre, rw);
    k1_pre<<<dim3(4, 64), 256>>>(x, b_pre);
    k1b2<<<1024, 256>>>(x, W_pre, b_pre);
    k3_right<<<dim3(1, 64), 256>>>();
    k4_route<<<1024, 256>>>(ridx, rside);
    k6_mma<<<dim3(2, 128), 128>>>(out);   // launch index 5 -> ncu capture slot
}

// round 9
// speedup vs baseline: 1.8110x; 1.0166x over previous
#include <cuda_runtime.h>
#include <cuda_fp16.h>
#include <math.h>

// ---------------------------------------------------------------------------
// DTree forward. Round 9: k6 CTA re-shaped to 128m x 64n (2 n-slices x 2
// m-halves): the m-warp pair's duplicate B loads dedup in L1, halving L2 B
// traffic (4.6 -> 2.3 GB) at identical HMMA count and 148-SM fill.
// k3 widened to 128 CTAs. Everything else as R8 (825 us).
// ---------------------------------------------------------------------------

#define BATCH   8192
#define DIN     512
#define D1      513
#define HP      272      // g_hh row stride in u32 (half2 pairs): 544 halves
#define NKT     17
#define NODES   127
#define LEAVES  128
#define DOUT    256
#define ITERS   (NKT * LEAVES)   // 2176

// prep_all block ranges
#define PB_LEAF 34816
#define PB_PRE  512
#define PB_RW   136
#define PB_NORM NODES

typedef unsigned long long u64;
typedef unsigned int u32;

// -------------------- scratch (device globals; no allocation) --------------
__device__ __align__(16) u32 g_hh[BATCH * HP];          // 8.9 MB packed half2 h
__device__ __align__(16) u32 g_Bp[LEAVES * NKT * 4096]; // 35.7 MB leaf B fragments
__device__ __align__(16) u32 g_Bpre[16 * 8192];         // 0.52 MB W_pre fragments
__device__ __align__(16) u32 g_Brw[NKT * 2048];         // 0.14 MB right_w fragments
__device__ u32 g_swh2[LEAVES * BATCH];                  // 4.2 MB (s,s) half2
__device__ float g_right[BATCH * 128];
__device__ float g_invh[BATCH];
__device__ float g_invw[NODES];
__device__ float g_entpart[1024];

// -------------------- helpers ----------------------------------------------
__device__ __forceinline__ u32 h2(float lo, float hi) {
    u32 r; asm("cvt.rn.f16x2.f32 %0, %1, %2;" : "=r"(r) : "f"(hi), "f"(lo)); return r;
}
__device__ __forceinline__ u32 hmul2(u32 a, u32 b) {
    u32 r; asm("mul.f16x2 %0, %1, %2;" : "=r"(r) : "r"(a), "r"(b)); return r;
}
__device__ __forceinline__ float2 h2f(u32 v) {
    __half2 h = *reinterpret_cast<__half2*>(&v);
    return __half22float2(h);
}
__device__ __forceinline__ void mma_f16(float* c, u32 a0, u32 a1, u32 a2, u32 a3,
                                        u32 b0, u32 b1) {
    asm volatile("mma.sync.aligned.m16n8k16.row.col.f32.f16.f16.f32 "
                 "{%0,%1,%2,%3}, {%4,%5,%6,%7}, {%8,%9}, {%0,%1,%2,%3};"
                 : "+f"(c[0]), "+f"(c[1]), "+f"(c[2]), "+f"(c[3])
                 : "r"(a0), "r"(a1), "r"(a2), "r"(a3), "r"(b0), "r"(b1));
}

// Fragment addressing convention (m16n8k16):
//   B frag u32 index = (((tile*NW + nw)*2 + ks)*2 + h)*128 + lane*4 + r
//   nt = h*2 + (r>>1); reg = r&1
//   n  = nw*32 + nt*8 + (lane>>2)
//   d  = kt*32 + ks*16 + (lane&3)*2 + reg*8   (value = half2(W[n][d], W[n][d+1]))

// ============================================================================
// k_prep_all: all weight preprocessing in one launch.
// ============================================================================
__global__ void k_prep_all(const float* __restrict__ Wl, const float* __restrict__ bl,
                           const float* __restrict__ Wp, const float* __restrict__ rw) {
    int blk = blockIdx.x;
    if (blk < PB_LEAF) {
        u32 o = (u32)blk * 256 + threadIdx.x;
        u32 r = o & 3, lane = (o >> 2) & 31;
        u32 h = (o >> 7) & 1, ks = (o >> 8) & 1, nw = (o >> 9) & 7;
        u32 t = o >> 12;
        u32 kt = t % 17, l = t / 17;
        u32 nt = h * 2 + (r >> 1), reg = r & 1;
        int n = (int)(nw * 32 + nt * 8 + (lane >> 2));
        int row = (int)(l * 256 + n);
        int d = (int)(kt * 32 + ks * 16 + (lane & 3) * 2 + reg * 8);
        float v0 = 0.0f, v1 = 0.0f;
        if (d < D1)           v0 = Wl[(size_t)row * D1 + d];
        else if (d == D1)     v0 = bl[row];
        if (d + 1 < D1)       v1 = Wl[(size_t)row * D1 + d + 1];
        else if (d + 1 == D1) v1 = bl[row];
        g_Bp[o] = h2(v0, v1);
        return;
    }
    blk -= PB_LEAF;
    if (blk < PB_PRE) {
        u32 o = (u32)blk * 256 + threadIdx.x;   // < 131072
        u32 r = o & 3, lane = (o >> 2) & 31;
        u32 h = (o >> 7) & 1, ks = (o >> 8) & 1, nw = (o >> 9) & 15;
        u32 kt = o >> 13;
        u32 nt = h * 2 + (r >> 1), reg = r & 1;
        int n = (int)(nw * 32 + nt * 8 + (lane >> 2));
        int d = (int)(kt * 32 + ks * 16 + (lane & 3) * 2 + reg * 8);
        g_Bpre[o] = h2(Wp[(size_t)n * DIN + d], Wp[(size_t)n * DIN + d + 1]);
        return;
    }
    blk -= PB_PRE;
    if (blk < PB_RW) {
        u32 o = (u32)blk * 256 + threadIdx.x;   // < 34816
        u32 r = o & 3, lane = (o >> 2) & 31;
        u32 h = (o >> 7) & 1, ks = (o >> 8) & 1, nw = (o >> 9) & 3;
        u32 kt = o >> 11;
        u32 nt = h * 2 + (r >> 1), reg = r & 1;
        int n = (int)(nw * 32 + nt * 8 + (lane >> 2));
        int d = (int)(kt * 32 + ks * 16 + (lane & 3) * 2 + reg * 8);
        float v0 = (n < NODES && d < D1)     ? rw[(size_t)n * D1 + d]     : 0.0f;
        float v1 = (n < NODES && d + 1 < D1) ? rw[(size_t)n * D1 + d + 1] : 0.0f;
        g_Brw[o] = h2(v0, v1);
        return;
    }
    blk -= PB_RW;
    {   // inverse row norm for node blk
        __shared__ float sm[8];
        int n = blk, tid = threadIdx.x;
        const float* wr = rw + (size_t)n * D1;
        float s = 0.0f;
        for (int d = tid; d < D1; d += 256) { float v = wr[d]; s += v * v; }
        #pragma unroll
        for (int o = 16; o > 0; o >>= 1) s += __shfl_xor_sync(0xffffffffu, s, o);
        if ((tid & 31) == 0) sm[tid >> 5] = s;
        __syncthreads();
        if (tid == 0) {
            float t = 0.0f;
            #pragma unroll
            for (int i = 0; i < 8; i++) t += sm[i];
            g_invw[n] = 1.0f / fmaxf(sqrtf(t), 1e-12f);
        }
    }
}

// ============================================================================
// k1: h[:,0:512] = relu(x @ W_pre[0:512]^T + b_pre) -> g_hh pairs 0..255
// ============================================================================
__global__ __launch_bounds__(256, 1) void k1_pre(const float* __restrict__ x,
                                                 const float* __restrict__ bp) {
    int tid = threadIdx.x, wid = tid >> 5, lane = tid & 31;
    int mw = wid >> 2, nwl = wid & 3;
    int m0 = blockIdx.y * 128;
    int nw = blockIdx.x * 4 + nwl;
    int rbase = m0 + mw * 64 + (lane >> 2);

    const u32* Bb = g_Bpre + (size_t)nw * 512 + lane * 4;
    const float* Xb = x + (size_t)rbase * DIN + (lane & 3) * 2;

    float acc[4][4][4];
    #pragma unroll
    for (int a = 0; a < 4; a++)
        #pragma unroll
        for (int b = 0; b < 4; b++)
            #pragma unroll
            for (int c = 0; c < 4; c++) acc[a][b][c] = 0.0f;

    uint4 bb[2][2][2];
    #pragma unroll
    for (int ks = 0; ks < 2; ks++)
        #pragma unroll
        for (int h = 0; h < 2; h++)
            bb[0][ks][h] = __ldg((const uint4*)(Bb + ks * 256 + h * 128));

    #pragma unroll 2
    for (int kt = 0; kt < 16; kt++) {
        int pb = kt & 1, nb = pb ^ 1;
        if (kt + 1 < 16) {
            const u32* t = Bb + (size_t)(kt + 1) * 8192;
            #pragma unroll
            for (int ks = 0; ks < 2; ks++)
                #pragma unroll
                for (int h = 0; h < 2; h++)
                    bb[nb][ks][h] = __ldg((const uint4*)(t + ks * 256 + h * 128));
        }
        u32 av[4][2][2][2];
        #pragma unroll
        for (int mt = 0; mt < 4; mt++)
            #pragma unroll
            for (int rhl = 0; rhl < 2; rhl++)
                #pragma unroll
                for (int ks = 0; ks < 2; ks++)
                    #pragma unroll
                    for (int reg = 0; reg < 2; reg++) {
                        float2 f = *(const float2*)(Xb + (size_t)(mt * 16 + rhl * 8) * DIN
                                                    + kt * 32 + ks * 16 + reg * 8);
                        av[mt][rhl][ks][reg] = h2(f.x, f.y);
                    }
        #pragma unroll
        for (int ks = 0; ks < 2; ks++)
            #pragma unroll
            for (int h = 0; h < 2; h++) {
                uint4 B = bb[pb][ks][h];
                #pragma unroll
                for (int mt = 0; mt < 4; mt++) {
                    mma_f16(acc[mt][h * 2],     av[mt][0][ks][0], av[mt][1][ks][0],
                            av[mt][0][ks][1], av[mt][1][ks][1], B.x, B.y);
                    mma_f16(acc[mt][h * 2 + 1], av[mt][0][ks][0], av[mt][1][ks][0],
                            av[mt][0][ks][1], av[mt][1][ks][1], B.z, B.w);
                }
            }
    }

    int ncol = blockIdx.x * 128 + nwl * 32 + (lane & 3) * 2;
    #pragma unroll
    for (int mt = 0; mt < 4; mt++)
        #pragma unroll
        for (int half = 0; half < 2; half++) {
            int row = rbase + mt * 16 + half * 8;
            #pragma unroll
            for (int nt = 0; nt < 4; nt++) {
                int n = ncol + nt * 8;
                float v0 = fmaxf(acc[mt][nt][half * 2]     + __ldg(bp + n),     0.0f);
                float v1 = fmaxf(acc[mt][nt][half * 2 + 1] + __ldg(bp + n + 1), 0.0f);
                g_hh[(size_t)row * HP + (n >> 1)] = h2(v0, v1);
            }
        }
}

// ============================================================================
// k1b2: h[:,512] dot + pad writes + row inverse-norm. One warp per row.
// ============================================================================
__global__ void k1b2(const float* __restrict__ x, const float* __restrict__ Wp,
                     const float* __restrict__ bp) {
    int w = threadIdx.x >> 5, lane = threadIdx.x & 31;
    int b = blockIdx.x * 8 + w;
    const float* xr = x + (size_t)b * DIN;
    const float* wr = Wp + (size_t)512 * DIN;
    float s = 0.0f;
    #pragma unroll 4
    for (int d = lane; d < DIN; d += 32) s += xr[d] * wr[d];
    #pragma unroll
    for (int o = 16; o > 0; o >>= 1) s += __shfl_xor_sync(0xffffffffu, s, o);
    float h512 = fmaxf(s + __ldg(bp + 512), 0.0f);   // uniform across warp

    u32* row = g_hh + (size_t)b * HP;
    if (lane == 0) row[256] = h2(h512, 1.0f);
    else if (lane < 16) row[256 + lane] = 0u;

    float t = 0.0f;
    for (int i = lane; i < 256; i += 32) {
        float2 f = h2f(row[i]);
        t += f.x * f.x + f.y * f.y;
    }
    #pragma unroll
    for (int o = 16; o > 0; o >>= 1) t += __shfl_xor_sync(0xffffffffu, t, o);
    if (lane == 0) g_invh[b] = 1.0f / fmaxf(sqrtf(t + h512 * h512), 1e-12f);
}

// ============================================================================
// k3: right[b,n] = invh[b]*invw[n]*(h . right_w[n])  -- fp16 mma
// 128 CTAs x 128 thr: CTA tile 64m x 128n, one warp per 32-col n-slice.
// ============================================================================
__global__ __launch_bounds__(128, 2) void k3_right() {
    int tid = threadIdx.x, nwl = tid >> 5, lane = tid & 31;
    int m0 = blockIdx.x * 64;
    int rbase = m0 + (lane >> 2);

    const u32* Bb = g_Brw + (size_t)nwl * 512 + lane * 4;
    const u32* Hb = g_hh + (size_t)rbase * HP + (lane & 3);

    float acc[4][4][4];
    #pragma unroll
    for (int a = 0; a < 4; a++)
        #pragma unroll
        for (int b = 0; b < 4; b++)
            #pragma unroll
            for (int c = 0; c < 4; c++) acc[a][b][c] = 0.0f;

    #pragma unroll 1
    for (int kt = 0; kt < 17; kt++) {
        uint4 bb[2][2];
        #pragma unroll
        for (int ks = 0; ks < 2; ks++)
            #pragma unroll
            for (int h = 0; h < 2; h++)
                bb[ks][h] = __ldg((const uint4*)(Bb + (size_t)kt * 2048 + ks * 256 + h * 128));
        u32 hv[4][2][2][2];
        #pragma unroll
        for (int mt = 0; mt < 4; mt++)
            #pragma unroll
            for (int rhl = 0; rhl < 2; rhl++)
                #pragma unroll
                for (int ks = 0; ks < 2; ks++)
                    #pragma unroll
                    for (int reg = 0; reg < 2; reg++)
                        hv[mt][rhl][ks][reg] = __ldg(Hb + (size_t)(mt * 16 + rhl * 8) * HP
                                                     + kt * 16 + ks * 8 + reg * 4);
        #pragma unroll
        for (int ks = 0; ks < 2; ks++)
            #pragma unroll
            for (int h = 0; h < 2; h++) {
                uint4 B = bb[ks][h];
                #pragma unroll
                for (int mt = 0; mt < 4; mt++) {
                    mma_f16(acc[mt][h * 2],     hv[mt][0][ks][0], hv[mt][1][ks][0],
                            hv[mt][0][ks][1], hv[mt][1][ks][1], B.x, B.y);
                    mma_f16(acc[mt][h * 2 + 1], hv[mt][0][ks][0], hv[mt][1][ks][0],
                            hv[mt][0][ks][1], hv[mt][1][ks][1], B.z, B.w);
                }
            }
    }

    #pragma unroll
    for (int mt = 0; mt < 4; mt++)
        #pragma unroll
        for (int half = 0; half < 2; half++) {
            int row = rbase + mt * 16 + half * 8;
            float ih = g_invh[row];
            #pragma unroll
            for (int nt = 0; nt < 4; nt++) {
                int n = nwl * 32 + nt * 8 + (lane & 3) * 2;
                if (n < NODES)
                    g_right[(size_t)row * 128 + n] = acc[mt][nt][half * 2] * ih * g_invw[n];
                if (n + 1 < NODES)
                    g_right[(size_t)row * 128 + n + 1] = acc[mt][nt][half * 2 + 1] * ih * g_invw[n + 1];
            }
        }
}

// ============================================================================
// k4: routing -> g_swh2 (packed (s,s) half2, [l][b]), entropy partials
// ============================================================================
__global__ __launch_bounds__(256) void k4_route(const int* __restrict__ ridx,
                                                const int* __restrict__ rside) {
    __shared__ int s_idx[LEAVES * 7];
    __shared__ int s_side[LEAVES * 7];
    __shared__ float s_lr[8][128];
    __shared__ float s_ll[8][128];
    __shared__ float s_ent[8];

    int tid = threadIdx.x;
    for (int t = tid; t < LEAVES * 7; t += 256) { s_idx[t] = ridx[t]; s_side[t] = rside[t]; }
    __syncthreads();

    int w = tid / 32, lane = tid % 32;
    int b = blockIdx.x * 8 + w;

    for (int n = lane; n < NODES; n += 32) {
        float r = g_right[b * 128 + n];
        float rd = 0.5f * (1.0f - r);
        float ld = 0.5f * (1.0f + r);
        s_lr[w][n] = logf(fminf(fmaxf(rd, 0.01f), 0.99f));
        s_ll[w][n] = logf(fminf(fmaxf(ld, 0.01f), 0.99f));
    }
    __syncwarp();

    float ent = 0.0f;
    for (int li = lane; li < LEAVES; li += 32) {
        float lp = 0.0f;
        #pragma unroll
        for (int j = 0; j < 7; j++) {
            int node = s_idx[li * 7 + j];
            int side = s_side[li * 7 + j];
            lp += side ? s_ll[w][node] : s_lr[w][node];
        }
        float s = expf(lp);
        g_swh2[li * BATCH + b] = h2(s, s);
        ent -= s * lp;
    }
    #pragma unroll
    for (int o = 16; o > 0; o >>= 1) ent += __shfl_xor_sync(0xffffffffu, ent, o);
    if (lane == 0) s_ent[w] = ent;
    __syncthreads();
    if (tid == 0) {
        float t = 0.0f;
        #pragma unroll
        for (int i = 0; i < 8; i++) t += s_ent[i];
        g_entpart[blockIdx.x] = t;
    }
}

// ============================================================================
// k6: fp16 mma leaf contraction. 256 CTAs x 128 thr, CTA tile 128m x 64n:
// 2 n-slice warps x 2 m-half warps. The m-pair's duplicate B loads hit L1
// -> L2 B traffic halves vs R8 at identical HMMA count and SM fill.
// Scale reduction from g_entpart inline in epilogue (deterministic).
// ============================================================================
__global__ __launch_bounds__(128, 2) void k6_mma(float* __restrict__ out) {
    int tid = threadIdx.x, wid = tid >> 5, lane = tid & 31;
    int mw = wid >> 1, nwl = wid & 1;
    int m0 = blockIdx.y * 128;
    int nw = blockIdx.x * 2 + nwl;
    int rbase = m0 + mw * 64 + (lane >> 2);

    const u32* Bb = g_Bp + (size_t)nw * 512 + lane * 4;     // + tile*4096 (+ks*256+h*128)
    const u32* SWb = g_swh2 + rbase;
    const u32* Hb = g_hh + (size_t)rbase * HP + (lane & 3);

    float acc[4][4][4];
    #pragma unroll
    for (int a = 0; a < 4; a++)
        #pragma unroll
        for (int b = 0; b < 4; b++)
            #pragma unroll
            for (int c = 0; c < 4; c++) acc[a][b][c] = 0.0f;

    uint4 bb[2][2][2];       // [buf][ks][h]
    u32 sw[2][8];            // [buf][mt*2 + rhl]
    u32 hv[4][2][2][2];      // [mt][rhl][ks][reg]

    // preload it=0 (kt=0, l=0)
    #pragma unroll
    for (int ks = 0; ks < 2; ks++)
        #pragma unroll
        for (int h = 0; h < 2; h++)
            bb[0][ks][h] = __ldg((const uint4*)(Bb + ks * 256 + h * 128));
    #pragma unroll
    for (int j = 0; j < 8; j++)
        sw[0][j] = __ldg(SWb + (j >> 1) * 16 + (j & 1) * 8);

    int it = 0;
    #pragma unroll 1
    for (int kt = 0; kt < NKT; kt++) {
        #pragma unroll
        for (int mt = 0; mt < 4; mt++)
            #pragma unroll
            for (int rhl = 0; rhl < 2; rhl++)
                #pragma unroll
                for (int ks = 0; ks < 2; ks++)
                    #pragma unroll
                    for (int reg = 0; reg < 2; reg++)
                        hv[mt][rhl][ks][reg] = __ldg(Hb + (size_t)(mt * 16 + rhl * 8) * HP
                                                     + kt * 16 + ks * 8 + reg * 4);
        #pragma unroll 2
        for (int l = 0; l < LEAVES; l++) {
            int pb = l & 1, nb = pb ^ 1;
            int nit = it + 1;
            if (nit < ITERS) {
                int nl = nit & 127, nkt = nit >> 7;
                const u32* t = Bb + (size_t)(nl * 17 + nkt) * 4096;
                #pragma unroll
                for (int ks = 0; ks < 2; ks++)
                    #pragma unroll
                    for (int h = 0; h < 2; h++)
                        bb[nb][ks][h] = __ldg((const uint4*)(t + ks * 256 + h * 128));
                const u32* sp = SWb + (size_t)nl * BATCH;
                #pragma unroll
                for (int j = 0; j < 8; j++)
                    sw[nb][j] = __ldg(sp + (j >> 1) * 16 + (j & 1) * 8);
            }
            #pragma unroll
            for (int ks = 0; ks < 2; ks++) {
                u32 A0[4], A1[4], A2[4], A3[4];
                #pragma unroll
                for (int mt = 0; mt < 4; mt++) {
                    A0[mt] = hmul2(hv[mt][0][ks][0], sw[pb][mt * 2]);
                    A1[mt] = hmul2(hv[mt][1][ks][0], sw[pb][mt * 2 + 1]);
                    A2[mt] = hmul2(hv[mt][0][ks][1], sw[pb][mt * 2]);
                    A3[mt] = hmul2(hv[mt][1][ks][1], sw[pb][mt * 2 + 1]);
                }
                #pragma unroll
                for (int h = 0; h < 2; h++) {
                    uint4 B = bb[pb][ks][h];
                    #pragma unroll
                    for (int mt = 0; mt < 4; mt++) {
                        mma_f16(acc[mt][h * 2],     A0[mt], A1[mt], A2[mt], A3[mt], B.x, B.y);
                        mma_f16(acc[mt][h * 2 + 1], A0[mt], A1[mt], A2[mt], A3[mt], B.z, B.w);
                    }
                }
            }
            it++;
        }
    }

    // inline deterministic scale = 1 + (sum(entpart)/BATCH)/max_ent
    __shared__ float sm[128];
    {
        float s = 0.0f;
        #pragma unroll
        for (int i = 0; i < 8; i++) s += g_entpart[tid + i * 128];
        sm[tid] = s;
    }
    __syncthreads();
    #pragma unroll
    for (int st = 64; st > 0; st >>= 1) {
        if (tid < st) sm[tid] += sm[tid + st];
        __syncthreads();
    }
    float max_ent = (128.0f / 6.0f) * logf(6.0f);
    float sc = 1.0f + (sm[0] / (float)BATCH) / max_ent;

    int ncol = blockIdx.x * 64 + nwl * 32 + (lane & 3) * 2;
    #pragma unroll
    for (int mt = 0; mt < 4; mt++)
        #pragma unroll
        for (int half = 0; half < 2; half++) {
            int row = rbase + mt * 16 + half * 8;
            float* op = out + (size_t)row * DOUT + ncol;
            #pragma unroll
            for (int nt = 0; nt < 4; nt++) {
                float2 v;
                v.x = acc[mt][nt][half * 2] * sc;
                v.y = acc[mt][nt][half * 2 + 1] * sc;
                *(float2*)(op + nt * 8) = v;
            }
        }
}

// ============================================================================
extern "C" void kernel_launch(void* const* d_in, const int* in_sizes, int n_in,
                              void* d_out, int out_size) {
    const float* x      = (const float*)d_in[0];
    const float* W_pre  = (const float*)d_in[1];
    const float* b_pre  = (const float*)d_in[2];
    const float* rw     = (const float*)d_in[3];
    const float* W_leaf = (const float*)d_in[4];
    const float* b_leaf = (const float*)d_in[5];
    const int*   ridx   = (const int*)d_in[6];
    const int*   rside  = (const int*)d_in[7];
    float* out = (float*)d_out;

    k_prep_all<<<PB_LEAF + PB_PRE + PB_RW + PB_NORM, 256>>>(W_leaf, b_leaf, W_pre, rw);
    k1_pre<<<dim3(4, 64), 256>>>(x, b_pre);
    k1b2<<<1024, 256>>>(x, W_pre, b_pre);
    k3_right<<<128, 128>>>();
    k4_route<<<1024, 256>>>(ridx, rside);
    k6_mma<<<dim3(4, 64), 128>>>(out);   // launch index 5 -> ncu capture slot
}